// round 10
// baseline (speedup 1.0000x reference)
#include <cuda_runtime.h>
#include <math.h>
#include <stdint.h>

// Scratch: Q1 ping-pong in both layouts. [B,S,S], B=4,S=160 -> 102400
#define MAXQ 102400
#define MAXR 1024
__device__ __align__(16) float g_q1 [2][MAXQ];   // Q1[b,m,h]
__device__ __align__(16) float g_q1T[2][MAXQ];   // Q1[b,h,m]
__device__ int   g_excl[MAXQ];     // per (b,h): excluded t list (mask[b,t,h]==0 || t==h)
__device__ int   g_ecnt[MAXR];     // per (b,h): list length

__device__ __forceinline__ uint32_t smem_u32(const void* p) {
    uint32_t a;
    asm("{ .reg .u64 t; cvta.to.shared.u64 t, %1; cvt.u32.u64 %0, t; }" : "=r"(a) : "l"(p));
    return a;
}

__device__ __forceinline__ void mbar_wait(uint32_t bar_a, int phase) {
    uint32_t done;
    asm volatile(
        "{\n\t.reg .pred P;\n\t"
        "mbarrier.try_wait.parity.acquire.cta.shared::cta.b64 P, [%1], %2;\n\t"
        "selp.b32 %0, 1, 0, P;\n\t}"
        : "=r"(done) : "r"(bar_a), "r"(phase) : "memory");
    if (!done) {
        asm volatile(
            "{\n\t.reg .pred P1;\n\t"
            "W%=:\n\t"
            "mbarrier.try_wait.parity.acquire.cta.shared::cta.b64 P1, [%0], %1, 0x989680;\n\t"
            "@P1 bra D%=;\n\t"
            "bra W%=;\n\t"
            "D%=:\n\t}"
            :: "r"(bar_a), "r"(phase) : "memory");
    }
}

// Pre-pass: build per-(b,h) exclusion list.
__global__ void excl_build_kernel(const int* __restrict__ mask, int S)
{
    __shared__ int cnt;
    int t = threadIdx.x;
    int h = blockIdx.x % S;
    int b = blockIdx.x / S;
    int row = b * S + h;
    if (t == 0) cnt = 0;
    __syncthreads();
    if (t < S) {
        bool ex = (mask[(b * S + t) * S + h] == 0) || (t == h);
        if (ex) {
            int slot = atomicAdd(&cnt, 1);
            g_excl[row * S + slot] = t;
        }
    }
    __syncthreads();
    if (t == 0) g_ecnt[row] = cnt;
}

// ============================================================================
// Pipelined kernel (compile-time S). 128 threads; block = (b, m, half);
// 5 tiles of 16 h-rows, 2-stage TMA ring.
// ============================================================================
template<int MODE, int SS>
__global__ void __launch_bounds__(128)
mfvi_pipe(const float* __restrict__ se,
          const float* __restrict__ ss,
          const float* __restrict__ sc,
          const float* __restrict__ sg,
          const int* __restrict__ mask,
          float* __restrict__ out,
          int parity)
{
    constexpr int ROWS = 16;
    constexpr int FV   = SS / 4;          // float4 per row (40)
    constexpr int KK   = FV / 8;          // unrolled chunks per thread (5)
    constexpr int NTA  = SS / ROWS;       // tiles total per (b,m) (10)
    constexpr int NT   = NTA / 2;         // tiles per block (5)
    constexpr int STG  = 3 * ROWS * SS;   // floats per stage (7680)

    int blk  = blockIdx.x;
    int half = blk & 1;
    int m    = (blk >> 1) % SS;
    int b    = (blk >> 1) / SS;
    int T0   = half * NT;

    int tid  = threadIdx.x;
    int li   = tid & 7;
    int rt   = tid >> 3;                  // row in tile 0..15

    extern __shared__ float smbuf[];
    unsigned long long* bars = (unsigned long long*)smbuf;   // 2 barriers
    float* stages = smbuf + 32;                              // 2 x STG floats
    uint32_t bar0 = smem_u32(bars);

    if (tid == 0) {
        asm volatile("mbarrier.init.shared.b64 [%0], %1;" :: "r"(bar0),     "r"(1) : "memory");
        asm volatile("mbarrier.init.shared.b64 [%0], %1;" :: "r"(bar0 + 8), "r"(1) : "memory");
    }
    __syncthreads();

    const long mbase = ((long)(b * SS + m)) * SS * SS;   // score base for this (b,m)
    const int  nb    = ROWS * SS * 4;                    // bytes per tensor-tile

    // issue tile k into stage s  (thread 0 only)
    auto issue = [&](int k, int s) {
        uint32_t ba = bar0 + s * 8;
        float* st = stages + s * STG;
        long off = mbase + (long)(T0 + k) * ROWS * SS;
        asm volatile("mbarrier.arrive.expect_tx.shared.b64 _, [%0], %1;"
                     :: "r"(ba), "r"(3 * nb) : "memory");
        asm volatile("cp.async.bulk.shared::cluster.global.mbarrier::complete_tx::bytes [%0], [%1], %2, [%3];"
                     :: "r"(smem_u32(st)),              "l"(ss + off), "r"(nb), "r"(ba) : "memory");
        asm volatile("cp.async.bulk.shared::cluster.global.mbarrier::complete_tx::bytes [%0], [%1], %2, [%3];"
                     :: "r"(smem_u32(st + ROWS * SS)),  "l"(sc + off), "r"(nb), "r"(ba) : "memory");
        asm volatile("cp.async.bulk.shared::cluster.global.mbarrier::complete_tx::bytes [%0], [%1], %2, [%3];"
                     :: "r"(smem_u32(st + 2 * ROWS * SS)), "l"(sg + off), "r"(nb), "r"(ba) : "memory");
    };

    if (tid == 0) issue(0, 0);

    const float* __restrict__ q1_in  = g_q1 [parity & 1];
    const float* __restrict__ q1T_in = g_q1T[parity & 1];

    // m-constant Q1 row/col in registers (overlaps with first TMA)
    float4 rowv[KK], colv[KK];
    if (MODE != 0) {
        const float4* pr = (const float4*)(q1_in  + (b * SS + m) * SS);
        const float4* pc = (const float4*)(q1T_in + (b * SS + m) * SS);
        #pragma unroll
        for (int k = 0; k < KK; k++) {
            rowv[k] = __ldg(pr + li + 8 * k);
            colv[k] = __ldg(pc + li + 8 * k);
        }
    }

    int ph0 = 0, ph1 = 0;

    #pragma unroll 1
    for (int i = 0; i < NT; i++) {
        int s = i & 1;
        if (tid == 0 && i + 1 < NT) issue(i + 1, s ^ 1);

        mbar_wait(bar0 + s * 8, s ? ph1 : ph0);

        int h = (T0 + i) * ROWS + rt;
        const float* st   = stages + s * STG;
        const float* ss_r = st + rt * SS;
        const float* sc_r = st + ROWS * SS + rt * SS;
        const float* sg_r = st + 2 * ROWS * SS + rt * SS;
        const long hbase = ((long)(b * SS + h)) * SS;
        const float4* pss = (const float4*)ss_r;
        const float4* psc = (const float4*)sc_r;
        const float4* psg = (const float4*)sg_r;
        const float4* pqa = (const float4*)(q1T_in + hbase);

        float acc = 0.f;
        #pragma unroll
        for (int k = 0; k < KK; k++) {
            int v = li + 8 * k;
            float4 a4 = pss[v];
            float4 c4 = psc[v];
            float4 g4 = psg[v];
            if (MODE == 0) {
                #pragma unroll
                for (int j = 0; j < 4; j++)
                    acc += (&a4.x)[j] + (&c4.x)[j] + (&g4.x)[j];
            } else {
                float4 qa = __ldg(pqa + v);
                #pragma unroll
                for (int j = 0; j < 4; j++) {
                    acc += (&a4.x)[j] * (&qa.x)[j];
                    acc += (&c4.x)[j] * (&rowv[k].x)[j];
                    acc += (&g4.x)[j] * (&colv[k].x)[j];
                }
            }
        }

        // reduce within 8-lane group
        acc += __shfl_down_sync(0xffffffffu, acc, 4, 8);
        acc += __shfl_down_sync(0xffffffffu, acc, 2, 8);
        acc += __shfl_down_sync(0xffffffffu, acc, 1, 8);

        if (li == 0) {
            int idx = (b * SS + m) * SS + h;
            float f = 0.f;
            if (mask[idx] != 0) {
                if (MODE == 0) acc *= 0.5f;
                int row = b * SS + h;
                int cnt = g_ecnt[row];
                const float* qrow = q1_in  + (b * SS + m) * SS;
                const float* qcol = q1T_in + (b * SS + m) * SS;
                for (int e = 0; e < cnt; e++) {
                    int t = g_excl[row * SS + e];
                    if (MODE == 0)
                        acc -= 0.5f * (ss_r[t] + sc_r[t] + sg_r[t]);
                    else
                        acc -= ss_r[t] * q1T_in[hbase + t]
                             + sc_r[t] * qrow[t]
                             + sg_r[t] * qcol[t];
                }
                if (m != h) {   // t == m exclusion
                    if (MODE == 0)
                        acc -= 0.5f * (ss_r[m] + sc_r[m] + sg_r[m]);
                    else
                        acc -= ss_r[m] * q1T_in[hbase + m]
                             + sc_r[m] * qrow[m]
                             + sg_r[m] * qcol[m];
                }
                f = acc;
            }
            float q = se[idx] + f;
            if (MODE == 2) {
                out[(long)idx * 2 + 0] = 1.f / (1.f + expf(q));
                out[(long)idx * 2 + 1] = 1.f / (1.f + expf(-q));
            } else {
                float q1v = 1.f / (1.f + expf(-q));
                int ob = (parity ^ 1) & 1;
                g_q1 [ob][idx] = q1v;
                g_q1T[ob][(b * SS + h) * SS + m] = q1v;
            }
        }

        if (s) ph1 ^= 1; else ph0 ^= 1;
        __syncthreads();   // all consumers done -> stage s reusable at i+2
    }
}

// ============================================================================
// Generic fallback (R8 kernel) for S != 160
// ============================================================================
template<int MODE>
__global__ void __launch_bounds__(256, 4)
mfvi_fallback(const float* __restrict__ se,
              const float* __restrict__ ss,
              const float* __restrict__ sc,
              const float* __restrict__ sg,
              const int* __restrict__ mask,
              float* __restrict__ out,
              int S, int parity)
{
    const int RW = 4, HT = 32;
    int ntile = (S + HT - 1) / HT;
    int blk = blockIdx.x;
    int htile = blk % ntile;
    int m     = (blk / ntile) % S;
    int b     = blk / (ntile * S);
    int warp = threadIdx.x >> 5, lane = threadIdx.x & 31;
    int g = lane >> 3, li = lane & 7;
    int h = htile * HT + warp * RW + g;

    extern __shared__ float smbuf[];
    float* sm_row = smbuf;
    float* sm_col = smbuf + S;

    const float* __restrict__ q1_in  = g_q1 [parity & 1];
    const float* __restrict__ q1T_in = g_q1T[parity & 1];

    if (MODE != 0) {
        int nv = S >> 2;
        const float4* r4 = (const float4*)(q1_in  + (b * S + m) * S);
        const float4* c4 = (const float4*)(q1T_in + (b * S + m) * S);
        for (int i = threadIdx.x; i < 2 * nv; i += blockDim.x) {
            if (i < nv) ((float4*)sm_row)[i] = r4[i];
            else        ((float4*)sm_col)[i - nv] = c4[i - nv];
        }
        __syncthreads();
    }

    bool valid = (h < S);
    int FV = S >> 2;
    const long sbase = (((long)(b * S + m)) * S + h) * S;
    const long hbase = ((long)(b * S + h)) * S;
    const float4* p_ss = (const float4*)(ss + sbase);
    const float4* p_sc = (const float4*)(sc + sbase);
    const float4* p_sg = (const float4*)(sg + sbase);
    const float4* p_qa = (const float4*)(q1T_in + hbase);
    const float4* srow = (const float4*)sm_row;
    const float4* scol = (const float4*)sm_col;

    float acc = 0.f;
    if (valid) {
        #pragma unroll 5
        for (int v = li; v < FV; v += 8) {
            float4 vss = __ldcs(p_ss + v);
            float4 vsc = __ldcs(p_sc + v);
            float4 vsg = __ldcs(p_sg + v);
            if (MODE == 0) {
                #pragma unroll
                for (int j = 0; j < 4; j++)
                    acc += (&vss.x)[j] + (&vsc.x)[j] + (&vsg.x)[j];
            } else {
                float4 vqa = p_qa[v];
                float4 vr  = srow[v];
                float4 vc  = scol[v];
                #pragma unroll
                for (int j = 0; j < 4; j++) {
                    acc += (&vss.x)[j] * (&vqa.x)[j];
                    acc += (&vsc.x)[j] * (&vr.x)[j];
                    acc += (&vsg.x)[j] * (&vc.x)[j];
                }
            }
        }
    }
    acc += __shfl_down_sync(0xffffffffu, acc, 4, 8);
    acc += __shfl_down_sync(0xffffffffu, acc, 2, 8);
    acc += __shfl_down_sync(0xffffffffu, acc, 1, 8);

    if (li == 0 && valid) {
        int idx = (b * S + m) * S + h;
        float f = 0.f;
        if (mask[idx] != 0) {
            if (MODE == 0) acc *= 0.5f;
            int row = b * S + h;
            int cnt = g_ecnt[row];
            for (int i = 0; i < cnt; i++) {
                int t = g_excl[row * S + i];
                if (MODE == 0)
                    acc -= 0.5f * (ss[sbase + t] + sc[sbase + t] + sg[sbase + t]);
                else
                    acc -= ss[sbase + t] * q1T_in[hbase + t]
                         + sc[sbase + t] * sm_row[t]
                         + sg[sbase + t] * sm_col[t];
            }
            if (m != h) {
                if (MODE == 0)
                    acc -= 0.5f * (ss[sbase + m] + sc[sbase + m] + sg[sbase + m]);
                else
                    acc -= ss[sbase + m] * q1T_in[hbase + m]
                         + sc[sbase + m] * sm_row[m]
                         + sg[sbase + m] * sm_col[m];
            }
            f = acc;
        }
        float q = se[idx] + f;
        if (MODE == 2) {
            out[(long)idx * 2 + 0] = 1.f / (1.f + expf(q));
            out[(long)idx * 2 + 1] = 1.f / (1.f + expf(-q));
        } else {
            float q1v = 1.f / (1.f + expf(-q));
            int ob = (parity ^ 1) & 1;
            g_q1 [ob][idx] = q1v;
            g_q1T[ob][(b * S + h) * S + m] = q1v;
        }
    }
}

extern "C" void kernel_launch(void* const* d_in, const int* in_sizes, int n_in,
                              void* d_out, int out_size)
{
    const float* se = (const float*)d_in[0];
    const float* ss = (const float*)d_in[1];
    const float* sc = (const float*)d_in[2];
    const float* sg = (const float*)d_in[3];
    const int* mask = (const int*)d_in[4];
    float* out = (float*)d_out;

    int BSS = in_sizes[0];                  // B*S*S
    int S = in_sizes[1] / BSS;              // (B*S^3)/(B*S^2)
    int B = BSS / (S * S);

    excl_build_kernel<<<B * S, (S + 31) & ~31>>>(mask, S);

    if (S == 160) {
        constexpr int SS_ = 160;
        size_t smem = (32 + 2 * 3 * 16 * SS_) * sizeof(float);   // 61,568 B
        cudaFuncSetAttribute(mfvi_pipe<0, SS_>, cudaFuncAttributeMaxDynamicSharedMemorySize, (int)smem);
        cudaFuncSetAttribute(mfvi_pipe<1, SS_>, cudaFuncAttributeMaxDynamicSharedMemorySize, (int)smem);
        cudaFuncSetAttribute(mfvi_pipe<2, SS_>, cudaFuncAttributeMaxDynamicSharedMemorySize, (int)smem);
        dim3 grid(B * SS_ * 2);
        mfvi_pipe<0, SS_><<<grid, 128, smem>>>(se, ss, sc, sg, mask, out, 1);
        mfvi_pipe<1, SS_><<<grid, 128, smem>>>(se, ss, sc, sg, mask, out, 0);
        mfvi_pipe<2, SS_><<<grid, 128, smem>>>(se, ss, sc, sg, mask, out, 1);
    } else {
        int ntile = (S + 31) / 32;
        dim3 grid(B * S * ntile);
        size_t smem = 2 * (size_t)S * sizeof(float);
        mfvi_fallback<0><<<grid, 256, smem>>>(se, ss, sc, sg, mask, out, S, 1);
        mfvi_fallback<1><<<grid, 256, smem>>>(se, ss, sc, sg, mask, out, S, 0);
        mfvi_fallback<2><<<grid, 256, smem>>>(se, ss, sc, sg, mask, out, S, 1);
    }
}